// round 3
// baseline (speedup 1.0000x reference)
#include <cuda_runtime.h>
#include <math.h>

#define NMAX 50000
#define EMAX 800000
#define HID  32
#define DIN  128

// ---------------- scratch (static; no cudaMalloc allowed) ----------------
__device__ __align__(128) float g_y1[NMAX * HID];   // x @ W1_l.T
__device__ __align__(128) float g_r1[NMAX * HID];   // x @ W1_r.T
__device__ __align__(128) float g_z2[NMAX];         // h @ W2_l.T (scalar)
__device__ __align__(128) float g_r2[NMAX];         // h @ W2_r.T (scalar)
__device__ __align__(128) int   g_ideg[NMAX];
__device__ __align__(128) int   g_rowptr[NMAX + 1];
__device__ __align__(128) int   g_cur[NMAX];
__device__ __align__(128) int   g_col[EMAX];        // CSR column (src) ids
__device__ int g_is64;

// ---------------- packed f32x2 helpers ----------------
__device__ __forceinline__ unsigned long long fma2(unsigned long long a,
                                                   unsigned long long b,
                                                   unsigned long long c) {
    unsigned long long d;
    asm("fma.rn.f32x2 %0, %1, %2, %3;" : "=l"(d) : "l"(a), "l"(b), "l"(c));
    return d;
}
__device__ __forceinline__ float hsum2(unsigned long long a) {
    float lo, hi;
    asm("mov.b64 {%0, %1}, %2;" : "=f"(lo), "=f"(hi) : "l"(a));
    return lo + hi;
}

__device__ __forceinline__ int load_dst(const void* ei, int E, int e, int is64) {
    return is64 ? (int)((const long long*)ei)[E + e] : ((const int*)ei)[E + e];
}
__device__ __forceinline__ int load_src(const void* ei, int E, int e, int is64) {
    return is64 ? (int)((const long long*)ei)[e] : ((const int*)ei)[e];
}

// ================= kernel 1: projections + dtype detect + ideg zero ============
// 128 threads/block. Thread t owns output o=t&63 (o<32 -> W1_l row, else W1_r)
// and K-half h=t>>6; 64 weight floats register-resident. x staged in smem tiles.
#define NB 8
__global__ void __launch_bounds__(128) k_lin1(const float* __restrict__ x,
                                              const float* __restrict__ Wl,
                                              const float* __restrict__ Wr,
                                              const unsigned int* __restrict__ ei32,
                                              int n) {
    // edge-dtype detection (block 0): with little-endian int64 and ids < 2^31
    // every odd 32-bit word is zero.
    if (blockIdx.x == 0) {
        __shared__ int found;
        if (threadIdx.x == 0) found = 0;
        __syncthreads();
        for (int i = 1 + 2 * threadIdx.x; i < 4096; i += 2 * blockDim.x)
            if (ei32[i] != 0u) found = 1;  // benign race
        __syncthreads();
        if (threadIdx.x == 0) g_is64 = (found == 0) ? 1 : 0;
    }
    // zero degree histogram (grid-stride)
    for (int i = blockIdx.x * blockDim.x + threadIdx.x; i < n;
         i += gridDim.x * blockDim.x)
        g_ideg[i] = 0;

    __shared__ __align__(16) float sx[NB * DIN];
    __shared__ float sp[NB * 64];

    int t = threadIdx.x;
    int o = t & 63;
    int h = t >> 6;

    const float* wrow = (o < 32) ? (Wl + o * DIN) : (Wr + (o - 32) * DIN);
    wrow += h * 64;
    ulonglong2 wreg[16];
#pragma unroll
    for (int j = 0; j < 16; j++)
        wreg[j] = ((const ulonglong2*)wrow)[j];

    const float4* x4 = (const float4*)x;
    int nbatch = (n + NB - 1) / NB;

    for (int b = blockIdx.x; b < nbatch; b += gridDim.x) {
        int nb0 = b * NB;
#pragma unroll
        for (int i = 0; i < 2; i++) {
            int idx = t + i * 128;
            int nn = idx >> 5, k4 = idx & 31;
            float4 v = make_float4(0.f, 0.f, 0.f, 0.f);
            if (nb0 + nn < n) v = x4[(nb0 + nn) * 32 + k4];
            ((float4*)sx)[idx] = v;
        }
        __syncthreads();

        float sum[NB];
#pragma unroll
        for (int nn = 0; nn < NB; nn++) {
            const ulonglong2* xp = (const ulonglong2*)(sx + nn * DIN + h * 64);
            unsigned long long aA = 0ull, aB = 0ull;
#pragma unroll
            for (int j = 0; j < 16; j++) {
                ulonglong2 xv = xp[j];
                aA = fma2(xv.x, wreg[j].x, aA);
                aB = fma2(xv.y, wreg[j].y, aB);
            }
            sum[nn] = hsum2(aA) + hsum2(aB);
        }

        if (h == 1) {
#pragma unroll
            for (int nn = 0; nn < NB; nn++) sp[nn * 64 + o] = sum[nn];
        }
        __syncthreads();
        if (h == 0) {
#pragma unroll
            for (int nn = 0; nn < NB; nn++) {
                int node = nb0 + nn;
                if (node < n) {
                    float v = sum[nn] + sp[nn * 64 + o];
                    if (o < 32) g_y1[node * 32 + o] = v;
                    else        g_r1[node * 32 + (o - 32)] = v;
                }
            }
        }
    }
}

// ================= kernel 2: degree histogram ============
__global__ void k_hist(const void* __restrict__ ei, int E) {
    int is64 = g_is64;
    int stride = gridDim.x * blockDim.x;
    for (int e = blockIdx.x * blockDim.x + threadIdx.x; e < E; e += stride)
        atomicAdd(&g_ideg[load_dst(ei, E, e, is64)], 1);
}

// ================= kernel 3: exclusive scan -> row_ptr, cur ============
__global__ void __launch_bounds__(1024) k_scan(int n) {
    __shared__ int wsum[32];
    int t = threadIdx.x, lane = t & 31, wid = t >> 5;
    int carry = 0;
    for (int base = 0; base < n; base += 1024) {
        int i = base + t;
        int v = (i < n) ? g_ideg[i] : 0;
        int x = v;
#pragma unroll
        for (int o = 1; o < 32; o <<= 1) {
            int u = __shfl_up_sync(0xFFFFFFFFu, x, o);
            if (lane >= o) x += u;
        }
        if (lane == 31) wsum[wid] = x;
        __syncthreads();
        if (wid == 0) {
            int s = wsum[lane];
#pragma unroll
            for (int o = 1; o < 32; o <<= 1) {
                int u = __shfl_up_sync(0xFFFFFFFFu, s, o);
                if (lane >= o) s += u;
            }
            wsum[lane] = s;
        }
        __syncthreads();
        int excl = x - v + carry + (wid > 0 ? wsum[wid - 1] : 0);
        if (i < n) {
            g_rowptr[i] = excl;
            g_cur[i] = excl;
        }
        carry += wsum[31];
        __syncthreads();
    }
    if (t == 0) g_rowptr[n] = carry;
}

// ================= kernel 4: CSR fill ============
__global__ void k_fill(const void* __restrict__ ei, int E) {
    int is64 = g_is64;
    int stride = gridDim.x * blockDim.x;
    for (int e = blockIdx.x * blockDim.x + threadIdx.x; e < E; e += stride) {
        int s = load_src(ei, E, e, is64);
        int d = load_dst(ei, E, e, is64);
        int p = atomicAdd(&g_cur[d], 1);
        g_col[p] = s;
    }
}

// ================= kernel 5: layer-1 aggregation fused with node update ========
// Warp per dst node. lane: chunk c = lane&7 (float4 of the 32-dim row),
// slot = lane>>3 (4 edges in flight). Computes mean, h=relu(mean+b1+r1),
// z2 = h.W2l, r2 = h.W2r directly -> only 2 scalars written per node.
__global__ void __launch_bounds__(256) k_agg1(const float* __restrict__ b1,
                                              const float* __restrict__ W2l,
                                              const float* __restrict__ W2r,
                                              int n) {
    int w = (blockIdx.x * blockDim.x + threadIdx.x) >> 5;
    int lane = threadIdx.x & 31;
    if (w >= n) return;
    int start = g_rowptr[w], end = g_rowptr[w + 1];
    int c = lane & 7, slot = lane >> 3;

    float4 acc = make_float4(0.f, 0.f, 0.f, 0.f);
    for (int j = start + slot; j < end; j += 4) {
        int s = g_col[j];
        float4 v = ((const float4*)g_y1)[s * 8 + c];
        acc.x += v.x; acc.y += v.y; acc.z += v.z; acc.w += v.w;
    }
#pragma unroll
    for (int o = 8; o <= 16; o <<= 1) {
        acc.x += __shfl_xor_sync(0xFFFFFFFFu, acc.x, o);
        acc.y += __shfl_xor_sync(0xFFFFFFFFu, acc.y, o);
        acc.z += __shfl_xor_sync(0xFFFFFFFFu, acc.z, o);
        acc.w += __shfl_xor_sync(0xFFFFFFFFu, acc.w, o);
    }
    float invd = 1.0f / fmaxf((float)(end - start), 1.0f);
    float4 r  = ((const float4*)g_r1)[w * 8 + c];
    float4 bb = ((const float4*)b1)[c];
    float4 h;
    h.x = fmaxf(fmaf(acc.x, invd, bb.x + r.x), 0.0f);
    h.y = fmaxf(fmaf(acc.y, invd, bb.y + r.y), 0.0f);
    h.z = fmaxf(fmaf(acc.z, invd, bb.z + r.z), 0.0f);
    h.w = fmaxf(fmaf(acc.w, invd, bb.w + r.w), 0.0f);
    float4 wl = ((const float4*)W2l)[c];
    float4 wr = ((const float4*)W2r)[c];
    float zl = h.x * wl.x + h.y * wl.y + h.z * wl.z + h.w * wl.w;
    float zr = h.x * wr.x + h.y * wr.y + h.z * wr.z + h.w * wr.w;
#pragma unroll
    for (int o = 1; o <= 4; o <<= 1) {
        zl += __shfl_xor_sync(0xFFFFFFFFu, zl, o);
        zr += __shfl_xor_sync(0xFFFFFFFFu, zr, o);
    }
    if (lane == 0) {
        g_z2[w] = zl;
        g_r2[w] = zr;
    }
}

// ================= kernel 6: layer-2 aggregation fused with sigmoid output =====
// 8 threads per dst node.
__global__ void __launch_bounds__(256) k_agg2(float* __restrict__ out,
                                              const float* __restrict__ b2,
                                              int n) {
    int t = blockIdx.x * blockDim.x + threadIdx.x;
    int d = t >> 3, q = t & 7;
    if (d >= n) return;
    int start = g_rowptr[d], end = g_rowptr[d + 1];
    float s = 0.0f;
    for (int j = start + q; j < end; j += 8)
        s += g_z2[g_col[j]];
#pragma unroll
    for (int o = 1; o <= 4; o <<= 1)
        s += __shfl_xor_sync(0xFFFFFFFFu, s, o);
    if (q == 0) {
        float v = s / fmaxf((float)(end - start), 1.0f) + b2[0] + g_r2[d];
        out[d] = 1.0f / (1.0f + expf(-v));
    }
}

// ---------------- launch ----------------
extern "C" void kernel_launch(void* const* d_in, const int* in_sizes, int n_in,
                              void* d_out, int out_size) {
    const float* x   = (const float*)d_in[0];
    const void*  ei  = d_in[1];
    const float* W1l = (const float*)d_in[2];
    const float* b1  = (const float*)d_in[3];
    const float* W1r = (const float*)d_in[4];
    const float* W2l = (const float*)d_in[5];
    const float* b2  = (const float*)d_in[6];
    const float* W2r = (const float*)d_in[7];
    float* out = (float*)d_out;

    int n = in_sizes[0] / DIN;
    int E = in_sizes[1] / 2;
    if (n > NMAX) n = NMAX;
    if (E > EMAX) E = EMAX;

    k_lin1<<<888, 128>>>(x, W1l, W1r, (const unsigned int*)ei, n);
    k_hist<<<1024, 256>>>(ei, E);
    k_scan<<<1, 1024>>>(n);
    k_fill<<<1024, 256>>>(ei, E);
    k_agg1<<<(n * 32 + 255) / 256, 256>>>(b1, W2l, W2r, n);
    k_agg2<<<(n * 8 + 255) / 256, 256>>>(out, b2, n);
}

// round 4
// speedup vs baseline: 1.3754x; 1.3754x over previous
#include <cuda_runtime.h>
#include <math.h>

#define NMAX 50000
#define EMAX 800000
#define HID  32
#define DIN  128

// ---------------- scratch (static; no cudaMalloc allowed) ----------------
__device__ __align__(128) float g_y1[NMAX * HID];    // x @ W1_l.T
__device__ __align__(128) float g_r1[NMAX * HID];    // x @ W1_r.T
__device__ __align__(128) float g_agg1[NMAX * HID];  // edge-summed y1
__device__ __align__(128) float g_deg[NMAX];
__device__ __align__(128) float g_z2[NMAX];          // h @ W2_l.T
__device__ __align__(128) float g_r2[NMAX];          // h @ W2_r.T
__device__ __align__(128) float g_agg2[NMAX];
__device__ int g_is64;

// ---------------- helpers ----------------
__device__ __forceinline__ unsigned long long fma2(unsigned long long a,
                                                   unsigned long long b,
                                                   unsigned long long c) {
    unsigned long long d;
    asm("fma.rn.f32x2 %0, %1, %2, %3;" : "=l"(d) : "l"(a), "l"(b), "l"(c));
    return d;
}
__device__ __forceinline__ float hsum2(unsigned long long a) {
    float lo, hi;
    asm("mov.b64 {%0, %1}, %2;" : "=f"(lo), "=f"(hi) : "l"(a));
    return lo + hi;
}
__device__ __forceinline__ void red_add_v4(float* addr, float4 v) {
    asm volatile("red.global.add.v4.f32 [%0], {%1, %2, %3, %4};"
                 :: "l"(addr), "f"(v.x), "f"(v.y), "f"(v.z), "f"(v.w)
                 : "memory");
}
// load 4 consecutive src ids and 4 consecutive dst ids with vector loads
__device__ __forceinline__ void load_edges4(const void* ei, int E, int e0,
                                            int is64, int* s, int* d) {
    if (is64) {
        longlong4 sv = *(const longlong4*)((const long long*)ei + e0);
        longlong4 dv = *(const longlong4*)((const long long*)ei + E + e0);
        s[0] = (int)sv.x; s[1] = (int)sv.y; s[2] = (int)sv.z; s[3] = (int)sv.w;
        d[0] = (int)dv.x; d[1] = (int)dv.y; d[2] = (int)dv.z; d[3] = (int)dv.w;
    } else {
        int4 sv = *(const int4*)((const int*)ei + e0);
        int4 dv = *(const int4*)((const int*)ei + E + e0);
        s[0] = sv.x; s[1] = sv.y; s[2] = sv.z; s[3] = sv.w;
        d[0] = dv.x; d[1] = dv.y; d[2] = dv.z; d[3] = dv.w;
    }
}

// ================= kernel 0: zero scratch + edge-dtype detect ============
// int64 detection: ids < 2^31, so little-endian int64 => every odd word is 0.
__global__ void k_zero(const unsigned int* __restrict__ ei32, int n) {
    if (blockIdx.x == 0) {
        __shared__ int found;
        if (threadIdx.x == 0) found = 0;
        __syncthreads();
        for (int i = 1 + 2 * threadIdx.x; i < 4096; i += 2 * blockDim.x)
            if (ei32[i] != 0u) found = 1;  // benign race
        __syncthreads();
        if (threadIdx.x == 0) g_is64 = (found == 0) ? 1 : 0;
    }
    int tot = n * HID;
    int stride = gridDim.x * blockDim.x;
    for (int i = blockIdx.x * blockDim.x + threadIdx.x; i < tot; i += stride)
        g_agg1[i] = 0.0f;
    for (int i = blockIdx.x * blockDim.x + threadIdx.x; i < n; i += stride) {
        g_deg[i] = 0.0f;
        g_agg2[i] = 0.0f;
    }
}

// ================= kernel 1: fused projections, register-resident weights ====
// Thread t owns output o=t&63 (o<32 -> W1_l row, else W1_r) and K-half h=t>>6.
#define NB 8
__global__ void __launch_bounds__(128) k_lin1(const float* __restrict__ x,
                                              const float* __restrict__ Wl,
                                              const float* __restrict__ Wr,
                                              int n) {
    __shared__ __align__(16) float sx[NB * DIN];
    __shared__ float sp[NB * 64];

    int t = threadIdx.x;
    int o = t & 63;
    int h = t >> 6;

    const float* wrow = (o < 32) ? (Wl + o * DIN) : (Wr + (o - 32) * DIN);
    wrow += h * 64;
    ulonglong2 wreg[16];
#pragma unroll
    for (int j = 0; j < 16; j++)
        wreg[j] = ((const ulonglong2*)wrow)[j];

    const float4* x4 = (const float4*)x;
    int nbatch = (n + NB - 1) / NB;

    for (int b = blockIdx.x; b < nbatch; b += gridDim.x) {
        int nb0 = b * NB;
#pragma unroll
        for (int i = 0; i < 2; i++) {
            int idx = t + i * 128;
            int nn = idx >> 5, k4 = idx & 31;
            float4 v = make_float4(0.f, 0.f, 0.f, 0.f);
            if (nb0 + nn < n) v = x4[(nb0 + nn) * 32 + k4];
            ((float4*)sx)[idx] = v;
        }
        __syncthreads();

        float sum[NB];
#pragma unroll
        for (int nn = 0; nn < NB; nn++) {
            const ulonglong2* xp = (const ulonglong2*)(sx + nn * DIN + h * 64);
            unsigned long long aA = 0ull, aB = 0ull;
#pragma unroll
            for (int j = 0; j < 16; j++) {
                ulonglong2 xv = xp[j];
                aA = fma2(xv.x, wreg[j].x, aA);
                aB = fma2(xv.y, wreg[j].y, aB);
            }
            sum[nn] = hsum2(aA) + hsum2(aB);
        }

        if (h == 1) {
#pragma unroll
            for (int nn = 0; nn < NB; nn++) sp[nn * 64 + o] = sum[nn];
        }
        __syncthreads();
        if (h == 0) {
#pragma unroll
            for (int nn = 0; nn < NB; nn++) {
                int node = nb0 + nn;
                if (node < n) {
                    float v = sum[nn] + sp[nn * 64 + o];
                    if (o < 32) g_y1[node * 32 + o] = v;
                    else        g_r1[node * 32 + (o - 32)] = v;
                }
            }
        }
    }
}

// ================= kernel 2: layer-1 edge scatter, 4 edges x 1 chunk / thread =
// thread -> (group g of 4 edges, chunk c of 8 float4s). Vector edge loads,
// 4 independent gather chains, 4 independent REDs (MLP=4).
__global__ void __launch_bounds__(256) k_edge1(const void* __restrict__ ei, int E) {
    int is64 = g_is64;
    int ngroups = E >> 2;              // E divisible by 4 (tail handled below)
    int t = blockIdx.x * blockDim.x + threadIdx.x;
    int g = t >> 3, c = t & 7;

    if (g < ngroups) {
        int e0 = g * 4;
        int s[4], d[4];
        load_edges4(ei, E, e0, is64, s, d);
        float4 v[4];
#pragma unroll
        for (int i = 0; i < 4; i++)
            v[i] = ((const float4*)g_y1)[s[i] * 8 + c];
#pragma unroll
        for (int i = 0; i < 4; i++)
            red_add_v4(&g_agg1[d[i] * 32 + c * 4], v[i]);
        if (c == 0) {
#pragma unroll
            for (int i = 0; i < 4; i++)
                atomicAdd(&g_deg[d[i]], 1.0f);
        }
    } else if (g == ngroups) {         // tail edges (E % 4)
        for (int e = ngroups * 4; e < E; e++) {
            int s = is64 ? (int)((const long long*)ei)[e] : ((const int*)ei)[e];
            int d = is64 ? (int)((const long long*)ei)[E + e] : ((const int*)ei)[E + e];
            float4 v = ((const float4*)g_y1)[s * 8 + c];
            red_add_v4(&g_agg1[d * 32 + c * 4], v);
            if (c == 0) atomicAdd(&g_deg[d], 1.0f);
        }
    }
}

// ================= kernel 3: node update + scalar layer-2 projections =========
// 8 threads per node, chunk c = t&7. 6 shuffles total.
__global__ void __launch_bounds__(256) k_node1(const float* __restrict__ b1,
                                               const float* __restrict__ W2l,
                                               const float* __restrict__ W2r,
                                               int n) {
    int t = blockIdx.x * blockDim.x + threadIdx.x;
    int node = t >> 3, c = t & 7;
    if (node >= n) return;
    float invd = 1.0f / fmaxf(g_deg[node], 1.0f);
    float4 a = ((const float4*)g_agg1)[node * 8 + c];
    float4 r = ((const float4*)g_r1)[node * 8 + c];
    float4 bb = ((const float4*)b1)[c];
    float4 h;
    h.x = fmaxf(fmaf(a.x, invd, bb.x + r.x), 0.0f);
    h.y = fmaxf(fmaf(a.y, invd, bb.y + r.y), 0.0f);
    h.z = fmaxf(fmaf(a.z, invd, bb.z + r.z), 0.0f);
    h.w = fmaxf(fmaf(a.w, invd, bb.w + r.w), 0.0f);
    float4 wl = ((const float4*)W2l)[c];
    float4 wr = ((const float4*)W2r)[c];
    float zl = h.x * wl.x + h.y * wl.y + h.z * wl.z + h.w * wl.w;
    float zr = h.x * wr.x + h.y * wr.y + h.z * wr.z + h.w * wr.w;
#pragma unroll
    for (int o = 1; o <= 4; o <<= 1) {
        zl += __shfl_xor_sync(0xFFFFFFFFu, zl, o);
        zr += __shfl_xor_sync(0xFFFFFFFFu, zr, o);
    }
    if (c == 0) {
        g_z2[node] = zl;
        g_r2[node] = zr;
    }
}

// ================= kernel 4: layer-2 scalar edge scatter, 4 edges / thread ====
__global__ void __launch_bounds__(256) k_edge2(const void* __restrict__ ei, int E) {
    int is64 = g_is64;
    int ngroups = E >> 2;
    int g = blockIdx.x * blockDim.x + threadIdx.x;
    if (g < ngroups) {
        int e0 = g * 4;
        int s[4], d[4];
        load_edges4(ei, E, e0, is64, s, d);
        float z[4];
#pragma unroll
        for (int i = 0; i < 4; i++) z[i] = g_z2[s[i]];
#pragma unroll
        for (int i = 0; i < 4; i++) atomicAdd(&g_agg2[d[i]], z[i]);
    } else if (g == ngroups) {
        for (int e = ngroups * 4; e < E; e++) {
            int s = is64 ? (int)((const long long*)ei)[e] : ((const int*)ei)[e];
            int d = is64 ? (int)((const long long*)ei)[E + e] : ((const int*)ei)[E + e];
            atomicAdd(&g_agg2[d], g_z2[s]);
        }
    }
}

// ================= kernel 5: final sigmoid ============
__global__ void k_out(float* __restrict__ out, const float* __restrict__ b2, int n) {
    int i = blockIdx.x * blockDim.x + threadIdx.x;
    if (i < n) {
        float inv = 1.0f / fmaxf(g_deg[i], 1.0f);
        float v = fmaf(g_agg2[i], inv, b2[0] + g_r2[i]);
        out[i] = 1.0f / (1.0f + expf(-v));
    }
}

// ---------------- launch ----------------
extern "C" void kernel_launch(void* const* d_in, const int* in_sizes, int n_in,
                              void* d_out, int out_size) {
    const float* x   = (const float*)d_in[0];
    const void*  ei  = d_in[1];
    const float* W1l = (const float*)d_in[2];
    const float* b1  = (const float*)d_in[3];
    const float* W1r = (const float*)d_in[4];
    const float* W2l = (const float*)d_in[5];
    const float* b2  = (const float*)d_in[6];
    const float* W2r = (const float*)d_in[7];
    float* out = (float*)d_out;

    int n = in_sizes[0] / DIN;
    int E = in_sizes[1] / 2;
    if (n > NMAX) n = NMAX;
    if (E > EMAX) E = EMAX;

    k_zero<<<2048, 256>>>((const unsigned int*)ei, n);
    k_lin1<<<888, 128>>>(x, W1l, W1r, n);
    int ng1 = (E >> 2) + 1;                    // +1 block-slot for tail group
    k_edge1<<<(ng1 * 8 + 255) / 256, 256>>>(ei, E);
    k_node1<<<(n * 8 + 255) / 256, 256>>>(b1, W2l, W2r, n);
    k_edge2<<<(ng1 + 255) / 256, 256>>>(ei, E);
    k_out<<<(n + 255) / 256, 256>>>(out, b2, n);
}

// round 6
// speedup vs baseline: 1.5190x; 1.1045x over previous
#include <cuda_runtime.h>
#include <cuda_bf16.h>
#include <math.h>

#define NMAX 50000
#define EMAX 800000
#define HID  32
#define DIN  128

// ---------------- scratch (static; no cudaMalloc allowed) ----------------
__device__ __align__(128) __nv_bfloat16 g_y1b[NMAX * HID];   // x @ W1_l.T (bf16)
__device__ __align__(128) __nv_bfloat16 g_agg1b[NMAX * HID]; // bf16 edge sums
__device__ __align__(128) float g_r1[NMAX * HID];            // x @ W1_r.T (fp32)
__device__ __align__(128) float g_deg[NMAX];
__device__ __align__(128) float g_z2[NMAX];
__device__ __align__(128) float g_r2[NMAX];
__device__ __align__(128) float g_agg2[NMAX];
__device__ int g_is64;

// ---------------- helpers ----------------
__device__ __forceinline__ unsigned long long fma2(unsigned long long a,
                                                   unsigned long long b,
                                                   unsigned long long c) {
    unsigned long long d;
    asm("fma.rn.f32x2 %0, %1, %2, %3;" : "=l"(d) : "l"(a), "l"(b), "l"(c));
    return d;
}
__device__ __forceinline__ float hsum2(unsigned long long a) {
    float lo, hi;
    asm("mov.b64 {%0, %1}, %2;" : "=f"(lo), "=f"(hi) : "l"(a));
    return lo + hi;
}
// 16-byte reduction of 8 bf16 values
__device__ __forceinline__ void red_add_bf16x8(void* addr, uint4 v) {
#if !defined(__CUDA_ARCH__) || __CUDA_ARCH__ >= 900
    asm volatile("red.global.add.noftz.v4.bf16x2 [%0], {%1, %2, %3, %4};"
                 :: "l"(addr), "r"(v.x), "r"(v.y), "r"(v.z), "r"(v.w)
                 : "memory");
#else
    __nv_bfloat162* p = (__nv_bfloat162*)addr;
    atomicAdd(p + 0, *(__nv_bfloat162*)&v.x);
    atomicAdd(p + 1, *(__nv_bfloat162*)&v.y);
    atomicAdd(p + 2, *(__nv_bfloat162*)&v.z);
    atomicAdd(p + 3, *(__nv_bfloat162*)&v.w);
#endif
}
__device__ __forceinline__ void load_edges4(const void* ei, int E, int e0,
                                            int is64, int* s, int* d) {
    if (is64) {
        longlong4 sv = *(const longlong4*)((const long long*)ei + e0);
        longlong4 dv = *(const longlong4*)((const long long*)ei + E + e0);
        s[0] = (int)sv.x; s[1] = (int)sv.y; s[2] = (int)sv.z; s[3] = (int)sv.w;
        d[0] = (int)dv.x; d[1] = (int)dv.y; d[2] = (int)dv.z; d[3] = (int)dv.w;
    } else {
        int4 sv = *(const int4*)((const int*)ei + e0);
        int4 dv = *(const int4*)((const int*)ei + E + e0);
        s[0] = sv.x; s[1] = sv.y; s[2] = sv.z; s[3] = sv.w;
        d[0] = dv.x; d[1] = dv.y; d[2] = dv.z; d[3] = dv.w;
    }
}

// ================= kernel 1: projections + dtype detect + zero scratch ========
// Thread t owns output o=t&63 (o<32 -> W1_l row, else W1_r) and K-half h=t>>6;
// 64 weight floats register-resident; x staged through smem in 8-node tiles.
#define NB 8
__global__ void __launch_bounds__(128) k_lin1(const float* __restrict__ x,
                                              const float* __restrict__ Wl,
                                              const float* __restrict__ Wr,
                                              const unsigned int* __restrict__ ei32,
                                              int n) {
    // edge dtype detect: ids < 2^31 => little-endian int64 has odd words == 0
    if (blockIdx.x == 0) {
        __shared__ int found;
        if (threadIdx.x == 0) found = 0;
        __syncthreads();
        for (int i = 1 + 2 * threadIdx.x; i < 4096; i += 2 * blockDim.x)
            if (ei32[i] != 0u) found = 1;  // benign race
        __syncthreads();
        if (threadIdx.x == 0) g_is64 = (found == 0) ? 1 : 0;
    }
    // zero bf16 agg (as uint32), deg, agg2
    {
        int gtid = blockIdx.x * blockDim.x + threadIdx.x;
        int stride = gridDim.x * blockDim.x;
        unsigned int* a32 = (unsigned int*)g_agg1b;
        int tot = n * HID / 2;
        for (int i = gtid; i < tot; i += stride) a32[i] = 0u;
        for (int i = gtid; i < n; i += stride) {
            g_deg[i] = 0.0f;
            g_agg2[i] = 0.0f;
        }
    }

    __shared__ __align__(16) float sx[NB * DIN];
    __shared__ float sp[NB * 64];

    int t = threadIdx.x;
    int o = t & 63;
    int h = t >> 6;

    const float* wrow = (o < 32) ? (Wl + o * DIN) : (Wr + (o - 32) * DIN);
    wrow += h * 64;
    ulonglong2 wreg[16];
#pragma unroll
    for (int j = 0; j < 16; j++)
        wreg[j] = ((const ulonglong2*)wrow)[j];

    const float4* x4 = (const float4*)x;
    int nbatch = (n + NB - 1) / NB;

    for (int b = blockIdx.x; b < nbatch; b += gridDim.x) {
        int nb0 = b * NB;
#pragma unroll
        for (int i = 0; i < 2; i++) {
            int idx = t + i * 128;
            int nn = idx >> 5, k4 = idx & 31;
            float4 v = make_float4(0.f, 0.f, 0.f, 0.f);
            if (nb0 + nn < n) v = x4[(nb0 + nn) * 32 + k4];
            ((float4*)sx)[idx] = v;
        }
        __syncthreads();

        float sum[NB];
#pragma unroll
        for (int nn = 0; nn < NB; nn++) {
            const ulonglong2* xp = (const ulonglong2*)(sx + nn * DIN + h * 64);
            unsigned long long aA = 0ull, aB = 0ull;
#pragma unroll
            for (int j = 0; j < 16; j++) {
                ulonglong2 xv = xp[j];
                aA = fma2(xv.x, wreg[j].x, aA);
                aB = fma2(xv.y, wreg[j].y, aB);
            }
            sum[nn] = hsum2(aA) + hsum2(aB);
        }

        if (h == 1) {
#pragma unroll
            for (int nn = 0; nn < NB; nn++) sp[nn * 64 + o] = sum[nn];
        }
        __syncthreads();
        if (h == 0) {
#pragma unroll
            for (int nn = 0; nn < NB; nn++) {
                int node = nb0 + nn;
                if (node < n) {
                    float v = sum[nn] + sp[nn * 64 + o];
                    if (o < 32) g_y1b[node * 32 + o] = __float2bfloat16(v);
                    else        g_r1[node * 32 + (o - 32)] = v;
                }
            }
        }
    }
}

// ================= kernel 2: layer-1 edge scatter (bf16 payload) ==============
// thread -> (group g of 4 edges, 16B chunk c of the 64B bf16 row).
// 4 independent gathers + 4 independent v4.bf16x2 REDs per thread.
__global__ void __launch_bounds__(256) k_edge1(const void* __restrict__ ei, int E) {
    int is64 = g_is64;
    int ngroups = E >> 2;
    int t = blockIdx.x * blockDim.x + threadIdx.x;
    int g = t >> 2, c = t & 3;

    const uint4* y4 = (const uint4*)g_y1b;          // 16B = 8 bf16
    char* aggb = (char*)g_agg1b;

    if (g < ngroups) {
        int e0 = g * 4;
        int s[4], d[4];
        load_edges4(ei, E, e0, is64, s, d);
        uint4 v[4];
#pragma unroll
        for (int i = 0; i < 4; i++)
            v[i] = y4[s[i] * 4 + c];
#pragma unroll
        for (int i = 0; i < 4; i++)
            red_add_bf16x8(aggb + d[i] * 64 + c * 16, v[i]);
        if (c == 0) {
#pragma unroll
            for (int i = 0; i < 4; i++)
                atomicAdd(&g_deg[d[i]], 1.0f);
        }
    } else if (g == ngroups) {  // tail (E % 4)
        for (int e = ngroups * 4; e < E; e++) {
            int s = is64 ? (int)((const long long*)ei)[e] : ((const int*)ei)[e];
            int d = is64 ? (int)((const long long*)ei)[E + e] : ((const int*)ei)[E + e];
            uint4 v = y4[s * 4 + c];
            red_add_bf16x8(aggb + d * 64 + c * 16, v);
            if (c == 0) atomicAdd(&g_deg[d], 1.0f);
        }
    }
}

// ================= kernel 3: node update + scalar layer-2 projections =========
// 8 threads per node; thread owns 4 features (8B of bf16 agg, 16B of fp32 r1).
__global__ void __launch_bounds__(256) k_node1(const float* __restrict__ b1,
                                               const float* __restrict__ W2l,
                                               const float* __restrict__ W2r,
                                               int n) {
    int t = blockIdx.x * blockDim.x + threadIdx.x;
    int node = t >> 3, c = t & 7;
    if (node >= n) return;
    float invd = 1.0f / fmaxf(g_deg[node], 1.0f);
    uint2 ab = ((const uint2*)g_agg1b)[node * 8 + c];
    float2 a0 = __bfloat1622float2(*(__nv_bfloat162*)&ab.x);
    float2 a1 = __bfloat1622float2(*(__nv_bfloat162*)&ab.y);
    float4 r = ((const float4*)g_r1)[node * 8 + c];
    float4 bb = ((const float4*)b1)[c];
    float4 h;
    h.x = fmaxf(fmaf(a0.x, invd, bb.x + r.x), 0.0f);
    h.y = fmaxf(fmaf(a0.y, invd, bb.y + r.y), 0.0f);
    h.z = fmaxf(fmaf(a1.x, invd, bb.z + r.z), 0.0f);
    h.w = fmaxf(fmaf(a1.y, invd, bb.w + r.w), 0.0f);
    float4 wl = ((const float4*)W2l)[c];
    float4 wr = ((const float4*)W2r)[c];
    float zl = h.x * wl.x + h.y * wl.y + h.z * wl.z + h.w * wl.w;
    float zr = h.x * wr.x + h.y * wr.y + h.z * wr.z + h.w * wr.w;
#pragma unroll
    for (int o = 1; o <= 4; o <<= 1) {
        zl += __shfl_xor_sync(0xFFFFFFFFu, zl, o);
        zr += __shfl_xor_sync(0xFFFFFFFFu, zr, o);
    }
    if (c == 0) {
        g_z2[node] = zl;
        g_r2[node] = zr;
    }
}

// ================= kernel 4: layer-2 scalar edge scatter (fp32) ===============
__global__ void __launch_bounds__(256) k_edge2(const void* __restrict__ ei, int E) {
    int is64 = g_is64;
    int ngroups = E >> 2;
    int g = blockIdx.x * blockDim.x + threadIdx.x;
    if (g < ngroups) {
        int e0 = g * 4;
        int s[4], d[4];
        load_edges4(ei, E, e0, is64, s, d);
        float z[4];
#pragma unroll
        for (int i = 0; i < 4; i++) z[i] = g_z2[s[i]];
#pragma unroll
        for (int i = 0; i < 4; i++) atomicAdd(&g_agg2[d[i]], z[i]);
    } else if (g == ngroups) {
        for (int e = ngroups * 4; e < E; e++) {
            int s = is64 ? (int)((const long long*)ei)[e] : ((const int*)ei)[e];
            int d = is64 ? (int)((const long long*)ei)[E + e] : ((const int*)ei)[E + e];
            atomicAdd(&g_agg2[d], g_z2[s]);
        }
    }
}

// ================= kernel 5: final sigmoid ============
__global__ void k_out(float* __restrict__ out, const float* __restrict__ b2, int n) {
    int i = blockIdx.x * blockDim.x + threadIdx.x;
    if (i < n) {
        float inv = 1.0f / fmaxf(g_deg[i], 1.0f);
        float v = fmaf(g_agg2[i], inv, b2[0] + g_r2[i]);
        out[i] = 1.0f / (1.0f + expf(-v));
    }
}

// ---------------- launch ----------------
extern "C" void kernel_launch(void* const* d_in, const int* in_sizes, int n_in,
                              void* d_out, int out_size) {
    const float* x   = (const float*)d_in[0];
    const void*  ei  = d_in[1];
    const float* W1l = (const float*)d_in[2];
    const float* b1  = (const float*)d_in[3];
    const float* W1r = (const float*)d_in[4];
    const float* W2l = (const float*)d_in[5];
    const float* b2  = (const float*)d_in[6];
    const float* W2r = (const float*)d_in[7];
    float* out = (float*)d_out;

    int n = in_sizes[0] / DIN;
    int E = in_sizes[1] / 2;
    if (n > NMAX) n = NMAX;
    if (E > EMAX) E = EMAX;

    k_lin1<<<888, 128>>>(x, W1l, W1r, (const unsigned int*)ei, n);
    int nthr1 = E + 4;                 // +4 thread-slots for the tail group
    k_edge1<<<(nthr1 + 255) / 256, 256>>>(ei, E);
    k_node1<<<(n * 8 + 255) / 256, 256>>>(b1, W2l, W2r, n);
    int ng = (E >> 2) + 1;
    k_edge2<<<(ng + 255) / 256, 256>>>(ei, E);
    k_out<<<(n + 255) / 256, 256>>>(out, b2, n);
}